// round 16
// baseline (speedup 1.0000x reference)
#include <cuda_runtime.h>
#include <cuda_bf16.h>
#include <math.h>
#include <stdint.h>

// ---------------------------------------------------------------------------
// Problem constants
// ---------------------------------------------------------------------------
#define BATCH   32
#define NTOK    1280
#define NS_     1024
#define NT_     256
#define DIM     384
#define HEADS   8
#define HDIM    48
#define NKV     320
#define FFDIM   1536
#define ATT_SCALE 0.14433756729740643f
// ATT_SCALE * log2(e): softmax computed in base-2 domain
#define ATT_SC2  0.20823031926528282f

typedef __nv_bfloat16 bf16;

// ---------------------------------------------------------------------------
// Scratch (device globals; no allocation allowed)
// ---------------------------------------------------------------------------
__device__ bf16  g_xn [BATCH * NTOK * DIM];
__device__ bf16  g_qc [BATCH * NTOK * DIM];
__device__ bf16  g_kc [BATCH * NKV  * DIM];
__device__ bf16  g_vc [BATCH * NKV  * DIM];
__device__ bf16  g_Q  [BATCH * NTOK * DIM];
__device__ bf16  g_K  [BATCH * NKV  * DIM];
__device__ bf16  g_V  [BATCH * NKV  * DIM];
__device__ float g_x2 [BATCH * NTOK * DIM];
__device__ bf16  g_h1 [BATCH * NTOK * FFDIM];
__device__ bf16  g_wq [DIM * DIM];
__device__ bf16  g_wk [DIM * DIM];
__device__ bf16  g_wv [DIM * DIM];
__device__ bf16  g_w1 [FFDIM * DIM];
__device__ bf16  g_w2 [DIM * FFDIM];

// ---------------------------------------------------------------------------
// Helpers
// ---------------------------------------------------------------------------
__device__ __forceinline__ void mma_bf16(float* c, const uint32_t* a, const uint32_t* b) {
    asm volatile(
        "mma.sync.aligned.m16n8k16.row.col.f32.bf16.bf16.f32 "
        "{%0,%1,%2,%3}, {%4,%5,%6,%7}, {%8,%9}, {%0,%1,%2,%3};"
        : "+f"(c[0]), "+f"(c[1]), "+f"(c[2]), "+f"(c[3])
        : "r"(a[0]), "r"(a[1]), "r"(a[2]), "r"(a[3]), "r"(b[0]), "r"(b[1]));
}

__device__ __forceinline__ void ldsm_x4(uint32_t addr, uint32_t* r) {
    asm volatile("ldmatrix.sync.aligned.m8n8.x4.shared.b16 {%0,%1,%2,%3}, [%4];"
        : "=r"(r[0]), "=r"(r[1]), "=r"(r[2]), "=r"(r[3]) : "r"(addr));
}

__device__ __forceinline__ void ldsm_x4_t(uint32_t addr, uint32_t* r) {
    asm volatile("ldmatrix.sync.aligned.m8n8.x4.trans.shared.b16 {%0,%1,%2,%3}, [%4];"
        : "=r"(r[0]), "=r"(r[1]), "=r"(r[2]), "=r"(r[3]) : "r"(addr));
}

__device__ __forceinline__ float ex2f(float x) {
    float r;
    asm("ex2.approx.f32 %0, %1;" : "=f"(r) : "f"(x));
    return r;
}

__device__ __forceinline__ uint32_t pack_bf2(float lo, float hi) {
    __nv_bfloat162 p = __floats2bfloat162_rn(lo, hi);
    return *(uint32_t*)&p;
}

#define CP_A16(dst, src) \
    asm volatile("cp.async.ca.shared.global [%0], [%1], 16;" :: "r"(dst), "l"(src))
#define CP_COMMIT() asm volatile("cp.async.commit_group;")
#define CP_WAIT1()  asm volatile("cp.async.wait_group 1;")
#define CP_WAIT0()  asm volatile("cp.async.wait_group 0;")

// ---------------------------------------------------------------------------
// LayerNorm body: one warp per token, float4 loads, bf16 packed stores.
// ---------------------------------------------------------------------------
__device__ __forceinline__ void ln_body(const float* __restrict__ x,
                                        const float* __restrict__ g,
                                        const float* __restrict__ b,
                                        bf16* __restrict__ out,
                                        int tok, int lane) {
    const float* xp = x + (size_t)tok * DIM;
    float4 v[3];
    float s = 0.0f, ss = 0.0f;
#pragma unroll
    for (int i = 0; i < 3; i++) {
        v[i] = *(const float4*)(xp + (lane + 32 * i) * 4);
        s  += v[i].x + v[i].y + v[i].z + v[i].w;
        ss += v[i].x * v[i].x + v[i].y * v[i].y + v[i].z * v[i].z + v[i].w * v[i].w;
    }
#pragma unroll
    for (int o = 16; o > 0; o >>= 1) {
        s  += __shfl_xor_sync(0xffffffffu, s,  o);
        ss += __shfl_xor_sync(0xffffffffu, ss, o);
    }
    float mean = s * (1.0f / DIM);
    float var  = ss * (1.0f / DIM) - mean * mean;
    float rstd = rsqrtf(var + 1e-5f);
    bf16* op = out + (size_t)tok * DIM;
#pragma unroll
    for (int i = 0; i < 3; i++) {
        int c = (lane + 32 * i) * 4;
        float4 gg = *(const float4*)(g + c);
        float4 bb = *(const float4*)(b + c);
        uint2 w;
        w.x = pack_bf2((v[i].x - mean) * rstd * gg.x + bb.x,
                       (v[i].y - mean) * rstd * gg.y + bb.y);
        w.y = pack_bf2((v[i].z - mean) * rstd * gg.z + bb.z,
                       (v[i].w - mean) * rstd * gg.w + bb.w);
        *(uint2*)(op + c) = w;
    }
}

// LN2 standalone
__global__ void ln_kernel(const float* __restrict__ x, const float* __restrict__ g,
                          const float* __restrict__ b, bf16* __restrict__ out) {
    int tok  = (blockIdx.x * 256 + threadIdx.x) >> 5;
    ln_body(x, g, b, out, tok, threadIdx.x & 31);
}

// ---------------------------------------------------------------------------
// Fused: weight conversion (blocks 0..1583) + LN1 (blocks 1584..6703)
// ---------------------------------------------------------------------------
__global__ void cvt_ln1(const float* __restrict__ s0, bf16* __restrict__ d0,
                        const float* __restrict__ s1, bf16* __restrict__ d1,
                        const float* __restrict__ s2, bf16* __restrict__ d2,
                        const float* __restrict__ s3, bf16* __restrict__ d3,
                        const float* __restrict__ s4, bf16* __restrict__ d4,
                        const float* __restrict__ x, const float* __restrict__ lg,
                        const float* __restrict__ lb, bf16* __restrict__ xo) {
    if (blockIdx.x < 1584) {
        int i = blockIdx.x * 256 + threadIdx.x;
        const float* s; bf16* d;
        if      (i <  36864) { s = s0; d = d0; }
        else if (i <  73728) { s = s1; d = d1; i -=  36864; }
        else if (i < 110592) { s = s2; d = d2; i -=  73728; }
        else if (i < 258048) { s = s3; d = d3; i -= 110592; }
        else                 { s = s4; d = d4; i -= 258048; }
        float4 v = ((const float4*)s)[i];
        uint2 o;
        o.x = pack_bf2(v.x, v.y);
        o.y = pack_bf2(v.z, v.w);
        ((uint2*)d)[i] = o;
    } else {
        int tok = ((blockIdx.x - 1584) * 256 + threadIdx.x) >> 5;
        ln_body(x, lg, lb, xo, tok, threadIdx.x & 31);
    }
}

// ---------------------------------------------------------------------------
// Depthwise 3x3 conv core (2 channels/thread, bf16x2 words)
// ---------------------------------------------------------------------------
__device__ __forceinline__ void dw_body(
    const bf16* __restrict__ in, const float* __restrict__ w,
    const float* __restrict__ cb, const float* __restrict__ bng,
    const float* __restrict__ bnb, bf16* __restrict__ out,
    int blk, int hw_in, int hw_out, int stride,
    int in_boff, int out_boff, int out_bstride) {
    int c   = threadIdx.x * 2;
    int ox  = blk % hw_out;
    int oy  = (blk / hw_out) % hw_out;
    int b   = blk / (hw_out * hw_out);
    const bf16* ip = in + (size_t)b * (NTOK * DIM) + (size_t)in_boff * DIM;
    float acc0 = cb[c], acc1 = cb[c + 1];
#pragma unroll
    for (int ky = 0; ky < 3; ky++) {
        int iy = oy * stride - 1 + ky;
        if (iy < 0 || iy >= hw_in) continue;
#pragma unroll
        for (int kx = 0; kx < 3; kx++) {
            int ix = ox * stride - 1 + kx;
            if (ix < 0 || ix >= hw_in) continue;
            uint32_t raw = *(const uint32_t*)(ip + (size_t)(iy * hw_in + ix) * DIM + c);
            __nv_bfloat162 pv = *(__nv_bfloat162*)&raw;
            int j = ky * 3 + kx;
            acc0 += __bfloat162float(pv.x) * w[c * 9 + j];
            acc1 += __bfloat162float(pv.y) * w[(c + 1) * 9 + j];
        }
    }
    float rs = rsqrtf(1.0f + 1e-5f);
    float o0 = acc0 * (bng[c] * rs)     + bnb[c];
    float o1 = acc1 * (bng[c + 1] * rs) + bnb[c + 1];
    *(uint32_t*)(out + (size_t)b * out_bstride + (size_t)(out_boff + oy * hw_out + ox) * DIM + c)
        = pack_bf2(o0, o1);
}

// All 6 conv geometries in ONE launch; grid = 40960 (q) + 10240 (k) + 10240 (v)
__global__ void dwconv_all(const bf16* __restrict__ in,
                           const float* __restrict__ wq, const float* __restrict__ cbq,
                           const float* __restrict__ gq, const float* __restrict__ bbq,
                           const float* __restrict__ wk, const float* __restrict__ cbk,
                           const float* __restrict__ gk, const float* __restrict__ bbk,
                           const float* __restrict__ wv, const float* __restrict__ cbv,
                           const float* __restrict__ gv, const float* __restrict__ bbv,
                           bf16* __restrict__ outq, bf16* __restrict__ outk,
                           bf16* __restrict__ outv) {
    int blk = blockIdx.x;
    if (blk < BATCH * 1280) {                     // Q conv (stride 1)
        if (blk < BATCH * 1024)
            dw_body(in, wq, cbq, gq, bbq, outq, blk, 32, 32, 1, 0, 0, NTOK * DIM);
        else
            dw_body(in, wq, cbq, gq, bbq, outq, blk - BATCH * 1024, 16, 16, 1, 1024, 1024, NTOK * DIM);
        return;
    }
    blk -= BATCH * 1280;
    const float *w, *cb, *bng, *bnb; bf16* out;
    if (blk < BATCH * 320) { w = wk; cb = cbk; bng = gk; bnb = bbk; out = outk; }
    else { blk -= BATCH * 320; w = wv; cb = cbv; bng = gv; bnb = bbv; out = outv; }
    if (blk < BATCH * 256)
        dw_body(in, w, cb, bng, bnb, out, blk, 32, 16, 2, 0, 0, NKV * DIM);
    else
        dw_body(in, w, cb, bng, bnb, out, blk - BATCH * 256, 16, 8, 2, 1024, 256, NKV * DIM);
}

// ---------------------------------------------------------------------------
// cp.async 3-stage BF16 GEMM mainloop (identical to round-12 baseline)
// ---------------------------------------------------------------------------
#define BSTG 10240

__device__ __forceinline__ void gemm_load_stage_bf(
    uint32_t smem_u32, const bf16* Asrc, const bf16* Bsrc, int s, int k0) {
    uint32_t dA = smem_u32 + (uint32_t)(s * BSTG) * 2u;
    const bf16* pA = Asrc + k0;
    CP_A16(dA, pA);
    CP_A16(dA + 16u, pA + 8);
    uint32_t dB = smem_u32 + (uint32_t)(s * BSTG + 5120) * 2u;
    const bf16* pB = Bsrc + k0;
    CP_A16(dB, pB);
    CP_A16(dB + 16u, pB + 8);
}

struct GemmCtx {
    uint32_t a_base[4];
    uint32_t b_base[2];
    uint32_t stoff;
};

__device__ __forceinline__ void gemm_ctx_init(GemmCtx& cx, uint32_t smem_u32) {
    int t = threadIdx.x;
    int row = t >> 1, half = t & 1;
    cx.stoff = (uint32_t)(row * 40 + half * 16) * 2u;
    int lane = t & 31;
    int w = t >> 5;
    int wm = (w >> 2) * 64, wn = (w & 3) * 32;
    int arow = wm + ((lane >> 3) & 1) * 8 + (lane & 7);
    int akw  = (lane >> 4) * 4;
#pragma unroll
    for (int mt = 0; mt < 4; mt++)
        cx.a_base[mt] = smem_u32 + (uint32_t)(((arow + mt * 16) * 20 + akw) * 4);
    int brow = wn + ((lane >> 4) & 1) * 8 + (lane & 7);
    int bkw  = ((lane >> 3) & 1) * 4;
#pragma unroll
    for (int p = 0; p < 2; p++)
        cx.b_base[p] = smem_u32 + (uint32_t)((2560 + (brow + p * 16) * 20 + bkw) * 4);
}

__device__ __forceinline__ void gemm_mainloop(
    const GemmCtx& cx, uint32_t smem_u32,
    const bf16* Asrc, const bf16* Bsrc, int ntiles, float acc[4][4][4]) {
    gemm_load_stage_bf(smem_u32 + cx.stoff, Asrc, Bsrc, 0, 0);
    CP_COMMIT();
    gemm_load_stage_bf(smem_u32 + cx.stoff, Asrc, Bsrc, 1, 32);
    CP_COMMIT();
    for (int i = 0; i < ntiles; i++) {
        CP_WAIT1();
        __syncthreads();
        if (i + 2 < ntiles)
            gemm_load_stage_bf(smem_u32 + cx.stoff, Asrc, Bsrc, (i + 2) % 3, (i + 2) * 32);
        CP_COMMIT();
        uint32_t so = (uint32_t)((i % 3) * 20480);
#pragma unroll
        for (int ks = 0; ks < 2; ks++) {
            uint32_t af[4][4], bb[2][4];
#pragma unroll
            for (int mt = 0; mt < 4; mt++)
                ldsm_x4(cx.a_base[mt] + so + ks * 32, af[mt]);
#pragma unroll
            for (int p = 0; p < 2; p++)
                ldsm_x4(cx.b_base[p] + so + ks * 32, bb[p]);
#pragma unroll
            for (int mt = 0; mt < 4; mt++)
#pragma unroll
                for (int nt = 0; nt < 4; nt++) {
                    uint32_t bfr[2] = { bb[nt >> 1][(nt & 1) * 2], bb[nt >> 1][(nt & 1) * 2 + 1] };
                    mma_bf16(acc[mt][nt], af[mt], bfr);
                }
        }
    }
}

// FFN GEMMs. EPI: 1 = bias+GELU -> bf16, 2 = bias+residual -> fp32.
template<int EPI>
__global__ void __launch_bounds__(256, 2)
gemm_bf(const bf16* __restrict__ A, const bf16* __restrict__ W,
        const float* __restrict__ bias, const float* __restrict__ res,
        void* __restrict__ Cv, int M, int N, int K) {
    extern __shared__ bf16 smem_bf[];
    uint32_t smem_u32 = (uint32_t)__cvta_generic_to_shared(smem_bf);
    int n0 = blockIdx.x * 128, m0 = blockIdx.y * 128;
    int t = threadIdx.x;
    int row = t >> 1, half = t & 1;
    int lane = t & 31, g = lane >> 2, tig = lane & 3;
    int w = t >> 5;
    int wm = (w >> 2) * 64, wn = (w & 3) * 32;

    GemmCtx cx; gemm_ctx_init(cx, smem_u32);
    const bf16* Asrc = A + (size_t)(m0 + row) * K + half * 16;
    const bf16* Bsrc = W + (size_t)(n0 + row) * K + half * 16;
    float acc[4][4][4] = {};
    gemm_mainloop(cx, smem_u32, Asrc, Bsrc, K >> 5, acc);

#pragma unroll
    for (int mt = 0; mt < 4; mt++) {
#pragma unroll
        for (int nt = 0; nt < 4; nt++) {
            int rbase = m0 + wm + mt * 16 + g;
            int col = n0 + wn + nt * 8 + 2 * tig;
#pragma unroll
            for (int hh = 0; hh < 2; hh++) {
                int r = rbase + hh * 8;
                float v0 = acc[mt][nt][hh * 2 + 0] + bias[col];
                float v1 = acc[mt][nt][hh * 2 + 1] + bias[col + 1];
                if (EPI == 1) {
                    v0 = 0.5f * v0 * (1.0f + erff(v0 * 0.70710678118654752f));
                    v1 = 0.5f * v1 * (1.0f + erff(v1 * 0.70710678118654752f));
                }
                size_t gi = (size_t)r * N + col;
                if (EPI == 2) {
                    float* C = (float*)Cv;
                    *(float2*)(C + gi) = make_float2(v0 + res[gi], v1 + res[gi + 1]);
                } else {
                    bf16* C = (bf16*)Cv;
                    *(uint32_t*)(C + gi) = pack_bf2(v0, v1);
                }
            }
        }
    }
}

// Merged Q/K/V projection GEMM: grid (3, 480); by<320 -> Q, <400 -> K, else V.
__global__ void __launch_bounds__(256, 2)
gemm_proj(const bf16* __restrict__ Aq, const bf16* __restrict__ Wq, const float* __restrict__ bq, bf16* __restrict__ Cq,
          const bf16* __restrict__ Ak, const bf16* __restrict__ Wk, const float* __restrict__ bk, bf16* __restrict__ Ck,
          const bf16* __restrict__ Av, const bf16* __restrict__ Wv, const float* __restrict__ bv, bf16* __restrict__ Cv2) {
    extern __shared__ bf16 smem_bf[];
    uint32_t smem_u32 = (uint32_t)__cvta_generic_to_shared(smem_bf);
    int by = blockIdx.y;
    const bf16 *A, *W; const float* bias; bf16* C;
    if (by < 320)      { A = Aq; W = Wq; bias = bq; C = Cq; }
    else if (by < 400) { A = Ak; W = Wk; bias = bk; C = Ck; by -= 320; }
    else               { A = Av; W = Wv; bias = bv; C = Cv2; by -= 400; }

    int n0 = blockIdx.x * 128, m0 = by * 128;
    int t = threadIdx.x;
    int row = t >> 1, half = t & 1;
    int lane = t & 31, g = lane >> 2, tig = lane & 3;
    int w = t >> 5;
    int wm = (w >> 2) * 64, wn = (w & 3) * 32;

    GemmCtx cx; gemm_ctx_init(cx, smem_u32);
    const bf16* Asrc = A + (size_t)(m0 + row) * DIM + half * 16;
    const bf16* Bsrc = W + (size_t)(n0 + row) * DIM + half * 16;
    float acc[4][4][4] = {};
    gemm_mainloop(cx, smem_u32, Asrc, Bsrc, DIM >> 5, acc);

#pragma unroll
    for (int mt = 0; mt < 4; mt++) {
#pragma unroll
        for (int nt = 0; nt < 4; nt++) {
            int rbase = m0 + wm + mt * 16 + g;
            int col = n0 + wn + nt * 8 + 2 * tig;
#pragma unroll
            for (int hh = 0; hh < 2; hh++) {
                int r = rbase + hh * 8;
                float v0 = acc[mt][nt][hh * 2 + 0] + bias[col];
                float v1 = acc[mt][nt][hh * 2 + 1] + bias[col + 1];
                *(uint32_t*)(C + (size_t)r * DIM + col) = pack_bf2(v0, v1);
            }
        }
    }
}

// ---------------------------------------------------------------------------
// Fused flash attention, base-2 online softmax, cp.async K/V + ldmatrix.
// grid: (20, B*H): bx 0..15 search (nkv=320), 16..19 target (nkv=64).
// ---------------------------------------------------------------------------
__global__ void __launch_bounds__(128)
attn_fused(const bf16* __restrict__ Q, const bf16* __restrict__ Kg,
           const bf16* __restrict__ Vg, const float* __restrict__ x,
           float* __restrict__ x2) {
    __shared__ __align__(16) bf16 Qs[64][56];
    __shared__ __align__(16) bf16 Ks[2][64][56];
    __shared__ __align__(16) bf16 Vs[2][64][56];
    __shared__ __align__(16) bf16 Ps[4][16][72];

    int bh = blockIdx.y, b = bh >> 3, h = bh & 7;
    int bx = blockIdx.x;
    int q_base, kv_base, niter;
    if (bx < 16) { q_base = bx * 64;               kv_base = 0;   niter = 5; }
    else         { q_base = 1024 + (bx - 16) * 64; kv_base = 256; niter = 1; }

    int t = threadIdx.x;
    int w = t >> 5, lane = t & 31, g = lane >> 2, tig = lane & 3;
    int wrow = w * 16;

    uint32_t qs_u32 = (uint32_t)__cvta_generic_to_shared(&Qs[0][0]);
    uint32_t ks_u32 = (uint32_t)__cvta_generic_to_shared(&Ks[0][0][0]);
    uint32_t vs_u32 = (uint32_t)__cvta_generic_to_shared(&Vs[0][0][0]);

    for (int idx = t; idx < 384; idx += 128) {
        int r = idx / 6, c8 = (idx % 6) * 8;
        uint4 raw = *(const uint4*)(Q + (size_t)(b * NTOK + q_base + r) * DIM + h * HDIM + c8);
        *(uint2*)&Qs[r][c8]     = make_uint2(raw.x, raw.y);
        *(uint2*)&Qs[r][c8 + 4] = make_uint2(raw.z, raw.w);
    }

    {
        const bf16* kbase = Kg + (size_t)(b * NKV + kv_base) * DIM + h * HDIM;
        const bf16* vbase = Vg + (size_t)(b * NKV + kv_base) * DIM + h * HDIM;
#pragma unroll
        for (int j0 = 0; j0 < 768; j0 += 128) {
            int j = j0 + t;
            int hv = j >= 384;
            int jj = hv ? j - 384 : j;
            int r = jj / 6, c8 = (jj % 6) * 8;
            const bf16* src = (hv ? vbase : kbase) + (size_t)r * DIM + c8;
            uint32_t dst = (hv ? vs_u32 : ks_u32) + (uint32_t)((r * 56 + c8) * 2);
            CP_A16(dst, src);
        }
        CP_COMMIT();
    }
    __syncthreads();

    uint32_t qf[3][4];
    {
        uint32_t qaddr = qs_u32 + (uint32_t)(((wrow + (lane & 15)) * 56 + (lane >> 4) * 8) * 2);
#pragma unroll
        for (int kt = 0; kt < 3; kt++)
            ldsm_x4(qaddr + kt * 32, qf[kt]);
    }

    uint32_t kaddr0 = ks_u32 + (uint32_t)((((lane & 7) + ((lane >> 4) & 1) * 8) * 56
                                           + ((lane >> 3) & 1) * 8) * 2);
    uint32_t vaddr0 = vs_u32 + (uint32_t)(((lane & 15) * 56 + (lane >> 4) * 8) * 2);

    float m0r = -1e30f, m1r = -1e30f, l0 = 0.0f, l1 = 0.0f;
    float oacc[6][4] = {};
    uint32_t* Pw = (uint32_t*)&Ps[w][0][0];

    for (int i = 0; i < niter; i++) {
        CP_WAIT0();
        __syncthreads();

        if (i + 1 < niter) {
            int k0n = (i + 1) * 64;
            uint32_t bufo = (uint32_t)(((i + 1) & 1) * 7168);
            const bf16* kbase = Kg + (size_t)(b * NKV + kv_base + k0n) * DIM + h * HDIM;
            const bf16* vbase = Vg + (size_t)(b * NKV + kv_base + k0n) * DIM + h * HDIM;
#pragma unroll
            for (int j0 = 0; j0 < 768; j0 += 128) {
                int j = j0 + t;
                int hv = j >= 384;
                int jj = hv ? j - 384 : j;
                int r = jj / 6, c8 = (jj % 6) * 8;
                const bf16* src = (hv ? vbase : kbase) + (size_t)r * DIM + c8;
                uint32_t dst = (hv ? vs_u32 : ks_u32) + bufo + (uint32_t)((r * 56 + c8) * 2);
                CP_A16(dst, src);
            }
        }
        CP_COMMIT();

        uint32_t bufc = (uint32_t)((i & 1) * 7168);

        // S' = Q @ K^T * (scale*log2e)
        float sf[8][4] = {};
#pragma unroll
        for (int kt = 0; kt < 3; kt++) {
#pragma unroll
            for (int p = 0; p < 4; p++) {
                uint32_t kb[4];
                ldsm_x4(kaddr0 + bufc + (uint32_t)(p * 16 * 112 + kt * 32), kb);
                uint32_t b0[2] = { kb[0], kb[1] };
                uint32_t b1[2] = { kb[2], kb[3] };
                mma_bf16(sf[2 * p],     qf[kt], b0);
                mma_bf16(sf[2 * p + 1], qf[kt], b1);
            }
        }
#pragma unroll
        for (int nt = 0; nt < 8; nt++) {
            sf[nt][0] *= ATT_SC2; sf[nt][1] *= ATT_SC2;
            sf[nt][2] *= ATT_SC2; sf[nt][3] *= ATT_SC2;
        }

        float tm0 = -1e30f, tm1 = -1e30f;
#pragma unroll
        for (int nt = 0; nt < 8; nt++) {
            tm0 = fmaxf(tm0, fmaxf(sf[nt][0], sf[nt][1]));
            tm1 = fmaxf(tm1, fmaxf(sf[nt][2], sf[nt][3]));
        }
        tm0 = fmaxf(tm0, __shfl_xor_sync(0xffffffffu, tm0, 1));
        tm0 = fmaxf(tm0, __shfl_xor_sync(0xffffffffu, tm0, 2));
        tm1 = fmaxf(tm1, __shfl_xor_sync(0xffffffffu, tm1, 1));
        tm1 = fmaxf(tm1, __shfl_xor_sync(0xffffffffu, tm1, 2));
        float nm0 = fmaxf(m0r, tm0), nm1 = fmaxf(m1r, tm1);
        float f0 = ex2f(m0r - nm0), f1 = ex2f(m1r - nm1);
        m0r = nm0; m1r = nm1;
        l0 *= f0; l1 *= f1;
#pragma unroll
        for (int nt = 0; nt < 6; nt++) {
            oacc[nt][0] *= f0; oacc[nt][1] *= f0;
            oacc[nt][2] *= f1; oacc[nt][3] *= f1;
        }
#pragma unroll
        for (int nt = 0; nt < 8; nt++) {
            float p0 = ex2f(sf[nt][0] - m0r);
            float p1 = ex2f(sf[nt][1] - m0r);
            float p2 = ex2f(sf[nt][2] - m1r);
            float p3 = ex2f(sf[nt][3] - m1r);
            l0 += p0 + p1; l1 += p2 + p3;
            Pw[(g    ) * 36 + nt * 4 + tig] = pack_bf2(p0, p1);
            Pw[(g + 8) * 36 + nt * 4 + tig] = pack_bf2(p2, p3);
        }
        __syncwarp();

#pragma unroll
        for (int ks = 0; ks < 4; ks++) {
            uint32_t pa[4];
            pa[0] = Pw[(g    ) * 36 + ks * 8 + tig];
            pa[1] = Pw[(g + 8) * 36 + ks * 8 + tig];
            pa[2] = Pw[(g    ) * 36 + ks * 8 + tig + 4];
            pa[3] = Pw[(g + 8) * 36 + ks * 8 + tig + 4];
#pragma unroll
            for (int jv = 0; jv < 3; jv++) {
                uint32_t vv[4];
                ldsm_x4_t(vaddr0 + bufc + (uint32_t)(ks * 16 * 112 + jv * 32), vv);
                uint32_t b0[2] = { vv[0], vv[1] };
                uint32_t b1[2] = { vv[2], vv[3] };
                mma_bf16(oacc[2 * jv],     pa, b0);
                mma_bf16(oacc[2 * jv + 1], pa, b1);
            }
        }
        __syncwarp();
    }

    l0 += __shfl_xor_sync(0xffffffffu, l0, 1);
    l0 += __shfl_xor_sync(0xffffffffu, l0, 2);
    l1 += __shfl_xor_sync(0xffffffffu, l1, 1);
    l1 += __shfl_xor_sync(0xffffffffu, l1, 2);
    float inv0 = 1.0f / l0, inv1 = 1.0f / l1;
    int r0 = b * NTOK + q_base + wrow + g;
#pragma unroll
    for (int nt = 0; nt < 6; nt++) {
        int col = h * HDIM + nt * 8 + 2 * tig;
        size_t gi0 = (size_t)r0 * DIM + col;
        size_t gi1 = (size_t)(r0 + 8) * DIM + col;
        float2 xa = *(const float2*)(x + gi0);
        float2 xb = *(const float2*)(x + gi1);
        *(float2*)(x2 + gi0) = make_float2(xa.x + oacc[nt][0] * inv0, xa.y + oacc[nt][1] * inv0);
        *(float2*)(x2 + gi1) = make_float2(xb.x + oacc[nt][2] * inv1, xb.y + oacc[nt][3] * inv1);
    }
}

// ---------------------------------------------------------------------------
// Launch
// ---------------------------------------------------------------------------
extern "C" void kernel_launch(void* const* d_in, const int* in_sizes, int n_in,
                              void* d_out, int out_size) {
    (void)in_sizes; (void)n_in; (void)out_size;
    const float* x     = (const float*)d_in[0];
    const float* ln1_g = (const float*)d_in[1];
    const float* ln1_b = (const float*)d_in[2];
    const float* dwq_w = (const float*)d_in[3];
    const float* dwq_b = (const float*)d_in[4];
    const float* bnq_g = (const float*)d_in[5];
    const float* bnq_b = (const float*)d_in[6];
    const float* dwk_w = (const float*)d_in[7];
    const float* dwk_b = (const float*)d_in[8];
    const float* bnk_g = (const float*)d_in[9];
    const float* bnk_b = (const float*)d_in[10];
    const float* dwv_w = (const float*)d_in[11];
    const float* dwv_b = (const float*)d_in[12];
    const float* bnv_g = (const float*)d_in[13];
    const float* bnv_b = (const float*)d_in[14];
    const float* pq_w  = (const float*)d_in[15];
    const float* pq_b  = (const float*)d_in[16];
    const float* pk_w  = (const float*)d_in[17];
    const float* pk_b  = (const float*)d_in[18];
    const float* pv_w  = (const float*)d_in[19];
    const float* pv_b  = (const float*)d_in[20];
    const float* ln2_g = (const float*)d_in[21];
    const float* ln2_b = (const float*)d_in[22];
    const float* ff1_w = (const float*)d_in[23];
    const float* ff1_b = (const float*)d_in[24];
    const float* ff2_w = (const float*)d_in[25];
    const float* ff2_b = (const float*)d_in[26];
    float* out = (float*)d_out;

    bf16 *xn, *qc, *kc, *vc, *Q, *K, *V, *h1, *wq, *wk, *wv, *w1, *w2;
    float *x2;
    cudaGetSymbolAddress((void**)&xn, g_xn);
    cudaGetSymbolAddress((void**)&qc, g_qc);
    cudaGetSymbolAddress((void**)&kc, g_kc);
    cudaGetSymbolAddress((void**)&vc, g_vc);
    cudaGetSymbolAddress((void**)&Q,  g_Q);
    cudaGetSymbolAddress((void**)&K,  g_K);
    cudaGetSymbolAddress((void**)&V,  g_V);
    cudaGetSymbolAddress((void**)&x2, g_x2);
    cudaGetSymbolAddress((void**)&h1, g_h1);
    cudaGetSymbolAddress((void**)&wq, g_wq);
    cudaGetSymbolAddress((void**)&wk, g_wk);
    cudaGetSymbolAddress((void**)&wv, g_wv);
    cudaGetSymbolAddress((void**)&w1, g_w1);
    cudaGetSymbolAddress((void**)&w2, g_w2);

    cudaFuncSetAttribute(gemm_bf<1>, cudaFuncAttributeMaxDynamicSharedMemorySize, 61440);
    cudaFuncSetAttribute(gemm_bf<2>, cudaFuncAttributeMaxDynamicSharedMemorySize, 61440);
    cudaFuncSetAttribute(gemm_proj,  cudaFuncAttributeMaxDynamicSharedMemorySize, 61440);

    // 1. Weight conversion + LN1 (single fused launch)
    cvt_ln1<<<1584 + BATCH * NTOK / 8, 256>>>(pq_w, wq, pk_w, wk, pv_w, wv,
                                              ff1_w, w1, ff2_w, w2,
                                              x, ln1_g, ln1_b, xn);

    // 2. All depthwise convs in one launch (q 40960 + k 10240 + v 10240 blocks)
    dwconv_all<<<BATCH * 1280 + 2 * BATCH * 320, 192>>>(
        xn,
        dwq_w, dwq_b, bnq_g, bnq_b,
        dwk_w, dwk_b, bnk_g, bnk_b,
        dwv_w, dwv_b, bnv_g, bnv_b,
        qc, kc, vc);

    // 3. Q/K/V projections — single merged launch
    gemm_proj<<<dim3(3, 480), 256, 61440>>>(qc, wq, pq_b, Q,
                                            kc, wk, pk_b, K,
                                            vc, wv, pv_b, V);

    // 4. Fused flash attention (+ residual)
    attn_fused<<<dim3(20, BATCH * HEADS), 128>>>(Q, K, V, x, x2);

    // 5. LN2 + FFN
    ln_kernel<<<BATCH * NTOK / 8, 256>>>(x2, ln2_g, ln2_b, xn);
    gemm_bf<1><<<dim3(12, 320), 256, 61440>>>(xn, w1, ff1_b, nullptr, h1, BATCH * NTOK, FFDIM, DIM);
    gemm_bf<2><<<dim3(3, 320),  256, 61440>>>(h1, w2, ff2_b, x2, out, BATCH * NTOK, DIM, FFDIM);
}

// round 17
// speedup vs baseline: 1.0012x; 1.0012x over previous
#include <cuda_runtime.h>
#include <cuda_bf16.h>
#include <math.h>
#include <stdint.h>

// ---------------------------------------------------------------------------
// Problem constants
// ---------------------------------------------------------------------------
#define BATCH   32
#define NTOK    1280
#define NS_     1024
#define NT_     256
#define DIM     384
#define HEADS   8
#define HDIM    48
#define NKV     320
#define FFDIM   1536
#define ATT_SCALE 0.14433756729740643f
// ATT_SCALE * log2(e): softmax computed in base-2 domain
#define ATT_SC2  0.20823031926528282f

typedef __nv_bfloat16 bf16;

// ---------------------------------------------------------------------------
// Scratch (device globals; no allocation allowed)
// ---------------------------------------------------------------------------
__device__ bf16  g_xn [BATCH * NTOK * DIM];
__device__ bf16  g_qc [BATCH * NTOK * DIM];
__device__ bf16  g_kc [BATCH * NKV  * DIM];
__device__ bf16  g_vc [BATCH * NKV  * DIM];
__device__ bf16  g_Q  [BATCH * NTOK * DIM];
__device__ bf16  g_K  [BATCH * NKV  * DIM];
__device__ bf16  g_V  [BATCH * NKV  * DIM];
__device__ float g_x2 [BATCH * NTOK * DIM];
__device__ bf16  g_h1 [BATCH * NTOK * FFDIM];
__device__ bf16  g_wq [DIM * DIM];
__device__ bf16  g_wk [DIM * DIM];
__device__ bf16  g_wv [DIM * DIM];
__device__ bf16  g_w1 [FFDIM * DIM];
__device__ bf16  g_w2 [DIM * FFDIM];

// ---------------------------------------------------------------------------
// Helpers
// ---------------------------------------------------------------------------
__device__ __forceinline__ void mma_bf16(float* c, const uint32_t* a, const uint32_t* b) {
    asm volatile(
        "mma.sync.aligned.m16n8k16.row.col.f32.bf16.bf16.f32 "
        "{%0,%1,%2,%3}, {%4,%5,%6,%7}, {%8,%9}, {%0,%1,%2,%3};"
        : "+f"(c[0]), "+f"(c[1]), "+f"(c[2]), "+f"(c[3])
        : "r"(a[0]), "r"(a[1]), "r"(a[2]), "r"(a[3]), "r"(b[0]), "r"(b[1]));
}

__device__ __forceinline__ void ldsm_x4(uint32_t addr, uint32_t* r) {
    asm volatile("ldmatrix.sync.aligned.m8n8.x4.shared.b16 {%0,%1,%2,%3}, [%4];"
        : "=r"(r[0]), "=r"(r[1]), "=r"(r[2]), "=r"(r[3]) : "r"(addr));
}

__device__ __forceinline__ void ldsm_x4_t(uint32_t addr, uint32_t* r) {
    asm volatile("ldmatrix.sync.aligned.m8n8.x4.trans.shared.b16 {%0,%1,%2,%3}, [%4];"
        : "=r"(r[0]), "=r"(r[1]), "=r"(r[2]), "=r"(r[3]) : "r"(addr));
}

__device__ __forceinline__ float ex2f(float x) {
    float r;
    asm("ex2.approx.f32 %0, %1;" : "=f"(r) : "f"(x));
    return r;
}

__device__ __forceinline__ uint32_t pack_bf2(float lo, float hi) {
    __nv_bfloat162 p = __floats2bfloat162_rn(lo, hi);
    return *(uint32_t*)&p;
}

#define CP_A16(dst, src) \
    asm volatile("cp.async.ca.shared.global [%0], [%1], 16;" :: "r"(dst), "l"(src))
#define CP_COMMIT() asm volatile("cp.async.commit_group;")
#define CP_WAIT1()  asm volatile("cp.async.wait_group 1;")
#define CP_WAIT0()  asm volatile("cp.async.wait_group 0;")

// ---------------------------------------------------------------------------
// LayerNorm body: one warp per token, float4 loads, bf16 packed stores.
// ---------------------------------------------------------------------------
__device__ __forceinline__ void ln_body(const float* __restrict__ x,
                                        const float* __restrict__ g,
                                        const float* __restrict__ b,
                                        bf16* __restrict__ out,
                                        int tok, int lane) {
    const float* xp = x + (size_t)tok * DIM;
    float4 v[3];
    float s = 0.0f, ss = 0.0f;
#pragma unroll
    for (int i = 0; i < 3; i++) {
        v[i] = *(const float4*)(xp + (lane + 32 * i) * 4);
        s  += v[i].x + v[i].y + v[i].z + v[i].w;
        ss += v[i].x * v[i].x + v[i].y * v[i].y + v[i].z * v[i].z + v[i].w * v[i].w;
    }
#pragma unroll
    for (int o = 16; o > 0; o >>= 1) {
        s  += __shfl_xor_sync(0xffffffffu, s,  o);
        ss += __shfl_xor_sync(0xffffffffu, ss, o);
    }
    float mean = s * (1.0f / DIM);
    float var  = ss * (1.0f / DIM) - mean * mean;
    float rstd = rsqrtf(var + 1e-5f);
    bf16* op = out + (size_t)tok * DIM;
#pragma unroll
    for (int i = 0; i < 3; i++) {
        int c = (lane + 32 * i) * 4;
        float4 gg = *(const float4*)(g + c);
        float4 bb = *(const float4*)(b + c);
        uint2 w;
        w.x = pack_bf2((v[i].x - mean) * rstd * gg.x + bb.x,
                       (v[i].y - mean) * rstd * gg.y + bb.y);
        w.y = pack_bf2((v[i].z - mean) * rstd * gg.z + bb.z,
                       (v[i].w - mean) * rstd * gg.w + bb.w);
        *(uint2*)(op + c) = w;
    }
}

// LN2 standalone
__global__ void ln_kernel(const float* __restrict__ x, const float* __restrict__ g,
                          const float* __restrict__ b, bf16* __restrict__ out) {
    int tok  = (blockIdx.x * 256 + threadIdx.x) >> 5;
    ln_body(x, g, b, out, tok, threadIdx.x & 31);
}

// ---------------------------------------------------------------------------
// Fused: weight conversion (blocks 0..1583) + LN1 (blocks 1584..6703)
// ---------------------------------------------------------------------------
__global__ void cvt_ln1(const float* __restrict__ s0, bf16* __restrict__ d0,
                        const float* __restrict__ s1, bf16* __restrict__ d1,
                        const float* __restrict__ s2, bf16* __restrict__ d2,
                        const float* __restrict__ s3, bf16* __restrict__ d3,
                        const float* __restrict__ s4, bf16* __restrict__ d4,
                        const float* __restrict__ x, const float* __restrict__ lg,
                        const float* __restrict__ lb, bf16* __restrict__ xo) {
    if (blockIdx.x < 1584) {
        int i = blockIdx.x * 256 + threadIdx.x;
        const float* s; bf16* d;
        if      (i <  36864) { s = s0; d = d0; }
        else if (i <  73728) { s = s1; d = d1; i -=  36864; }
        else if (i < 110592) { s = s2; d = d2; i -=  73728; }
        else if (i < 258048) { s = s3; d = d3; i -= 110592; }
        else                 { s = s4; d = d4; i -= 258048; }
        float4 v = ((const float4*)s)[i];
        uint2 o;
        o.x = pack_bf2(v.x, v.y);
        o.y = pack_bf2(v.z, v.w);
        ((uint2*)d)[i] = o;
    } else {
        int tok = ((blockIdx.x - 1584) * 256 + threadIdx.x) >> 5;
        ln_body(x, lg, lb, xo, tok, threadIdx.x & 31);
    }
}

// ---------------------------------------------------------------------------
// Depthwise 3x3 conv core (2 channels/thread, bf16x2 words)
// ---------------------------------------------------------------------------
__device__ __forceinline__ void dw_body(
    const bf16* __restrict__ in, const float* __restrict__ w,
    const float* __restrict__ cb, const float* __restrict__ bng,
    const float* __restrict__ bnb, bf16* __restrict__ out,
    int blk, int hw_in, int hw_out, int stride,
    int in_boff, int out_boff, int out_bstride) {
    int c   = threadIdx.x * 2;
    int ox  = blk % hw_out;
    int oy  = (blk / hw_out) % hw_out;
    int b   = blk / (hw_out * hw_out);
    const bf16* ip = in + (size_t)b * (NTOK * DIM) + (size_t)in_boff * DIM;
    float acc0 = cb[c], acc1 = cb[c + 1];
#pragma unroll
    for (int ky = 0; ky < 3; ky++) {
        int iy = oy * stride - 1 + ky;
        if (iy < 0 || iy >= hw_in) continue;
#pragma unroll
        for (int kx = 0; kx < 3; kx++) {
            int ix = ox * stride - 1 + kx;
            if (ix < 0 || ix >= hw_in) continue;
            uint32_t raw = *(const uint32_t*)(ip + (size_t)(iy * hw_in + ix) * DIM + c);
            __nv_bfloat162 pv = *(__nv_bfloat162*)&raw;
            int j = ky * 3 + kx;
            acc0 += __bfloat162float(pv.x) * w[c * 9 + j];
            acc1 += __bfloat162float(pv.y) * w[(c + 1) * 9 + j];
        }
    }
    float rs = rsqrtf(1.0f + 1e-5f);
    float o0 = acc0 * (bng[c] * rs)     + bnb[c];
    float o1 = acc1 * (bng[c + 1] * rs) + bnb[c + 1];
    *(uint32_t*)(out + (size_t)b * out_bstride + (size_t)(out_boff + oy * hw_out + ox) * DIM + c)
        = pack_bf2(o0, o1);
}

// All 6 conv geometries in ONE launch; grid = 40960 (q) + 10240 (k) + 10240 (v)
__global__ void dwconv_all(const bf16* __restrict__ in,
                           const float* __restrict__ wq, const float* __restrict__ cbq,
                           const float* __restrict__ gq, const float* __restrict__ bbq,
                           const float* __restrict__ wk, const float* __restrict__ cbk,
                           const float* __restrict__ gk, const float* __restrict__ bbk,
                           const float* __restrict__ wv, const float* __restrict__ cbv,
                           const float* __restrict__ gv, const float* __restrict__ bbv,
                           bf16* __restrict__ outq, bf16* __restrict__ outk,
                           bf16* __restrict__ outv) {
    int blk = blockIdx.x;
    if (blk < BATCH * 1280) {                     // Q conv (stride 1)
        if (blk < BATCH * 1024)
            dw_body(in, wq, cbq, gq, bbq, outq, blk, 32, 32, 1, 0, 0, NTOK * DIM);
        else
            dw_body(in, wq, cbq, gq, bbq, outq, blk - BATCH * 1024, 16, 16, 1, 1024, 1024, NTOK * DIM);
        return;
    }
    blk -= BATCH * 1280;
    const float *w, *cb, *bng, *bnb; bf16* out;
    if (blk < BATCH * 320) { w = wk; cb = cbk; bng = gk; bnb = bbk; out = outk; }
    else { blk -= BATCH * 320; w = wv; cb = cbv; bng = gv; bnb = bbv; out = outv; }
    if (blk < BATCH * 256)
        dw_body(in, w, cb, bng, bnb, out, blk, 32, 16, 2, 0, 0, NKV * DIM);
    else
        dw_body(in, w, cb, bng, bnb, out, blk - BATCH * 256, 16, 8, 2, 1024, 256, NKV * DIM);
}

// ---------------------------------------------------------------------------
// cp.async 3-stage BF16 GEMM mainloop (identical to round-12 baseline)
// ---------------------------------------------------------------------------
#define BSTG 10240

__device__ __forceinline__ void gemm_load_stage_bf(
    uint32_t smem_u32, const bf16* Asrc, const bf16* Bsrc, int s, int k0) {
    uint32_t dA = smem_u32 + (uint32_t)(s * BSTG) * 2u;
    const bf16* pA = Asrc + k0;
    CP_A16(dA, pA);
    CP_A16(dA + 16u, pA + 8);
    uint32_t dB = smem_u32 + (uint32_t)(s * BSTG + 5120) * 2u;
    const bf16* pB = Bsrc + k0;
    CP_A16(dB, pB);
    CP_A16(dB + 16u, pB + 8);
}

struct GemmCtx {
    uint32_t a_base[4];
    uint32_t b_base[2];
    uint32_t stoff;
};

__device__ __forceinline__ void gemm_ctx_init(GemmCtx& cx, uint32_t smem_u32) {
    int t = threadIdx.x;
    int row = t >> 1, half = t & 1;
    cx.stoff = (uint32_t)(row * 40 + half * 16) * 2u;
    int lane = t & 31;
    int w = t >> 5;
    int wm = (w >> 2) * 64, wn = (w & 3) * 32;
    int arow = wm + ((lane >> 3) & 1) * 8 + (lane & 7);
    int akw  = (lane >> 4) * 4;
#pragma unroll
    for (int mt = 0; mt < 4; mt++)
        cx.a_base[mt] = smem_u32 + (uint32_t)(((arow + mt * 16) * 20 + akw) * 4);
    int brow = wn + ((lane >> 4) & 1) * 8 + (lane & 7);
    int bkw  = ((lane >> 3) & 1) * 4;
#pragma unroll
    for (int p = 0; p < 2; p++)
        cx.b_base[p] = smem_u32 + (uint32_t)((2560 + (brow + p * 16) * 20 + bkw) * 4);
}

__device__ __forceinline__ void gemm_mainloop(
    const GemmCtx& cx, uint32_t smem_u32,
    const bf16* Asrc, const bf16* Bsrc, int ntiles, float acc[4][4][4]) {
    gemm_load_stage_bf(smem_u32 + cx.stoff, Asrc, Bsrc, 0, 0);
    CP_COMMIT();
    gemm_load_stage_bf(smem_u32 + cx.stoff, Asrc, Bsrc, 1, 32);
    CP_COMMIT();
    for (int i = 0; i < ntiles; i++) {
        CP_WAIT1();
        __syncthreads();
        if (i + 2 < ntiles)
            gemm_load_stage_bf(smem_u32 + cx.stoff, Asrc, Bsrc, (i + 2) % 3, (i + 2) * 32);
        CP_COMMIT();
        uint32_t so = (uint32_t)((i % 3) * 20480);
#pragma unroll
        for (int ks = 0; ks < 2; ks++) {
            uint32_t af[4][4], bb[2][4];
#pragma unroll
            for (int mt = 0; mt < 4; mt++)
                ldsm_x4(cx.a_base[mt] + so + ks * 32, af[mt]);
#pragma unroll
            for (int p = 0; p < 2; p++)
                ldsm_x4(cx.b_base[p] + so + ks * 32, bb[p]);
#pragma unroll
            for (int mt = 0; mt < 4; mt++)
#pragma unroll
                for (int nt = 0; nt < 4; nt++) {
                    uint32_t bfr[2] = { bb[nt >> 1][(nt & 1) * 2], bb[nt >> 1][(nt & 1) * 2 + 1] };
                    mma_bf16(acc[mt][nt], af[mt], bfr);
                }
        }
    }
}

// FFN GEMMs. EPI: 1 = bias+GELU -> bf16, 2 = bias+residual -> fp32.
template<int EPI>
__global__ void __launch_bounds__(256, 2)
gemm_bf(const bf16* __restrict__ A, const bf16* __restrict__ W,
        const float* __restrict__ bias, const float* __restrict__ res,
        void* __restrict__ Cv, int M, int N, int K) {
    extern __shared__ bf16 smem_bf[];
    uint32_t smem_u32 = (uint32_t)__cvta_generic_to_shared(smem_bf);
    int n0 = blockIdx.x * 128, m0 = blockIdx.y * 128;
    int t = threadIdx.x;
    int row = t >> 1, half = t & 1;
    int lane = t & 31, g = lane >> 2, tig = lane & 3;
    int w = t >> 5;
    int wm = (w >> 2) * 64, wn = (w & 3) * 32;

    GemmCtx cx; gemm_ctx_init(cx, smem_u32);
    const bf16* Asrc = A + (size_t)(m0 + row) * K + half * 16;
    const bf16* Bsrc = W + (size_t)(n0 + row) * K + half * 16;
    float acc[4][4][4] = {};
    gemm_mainloop(cx, smem_u32, Asrc, Bsrc, K >> 5, acc);

#pragma unroll
    for (int mt = 0; mt < 4; mt++) {
#pragma unroll
        for (int nt = 0; nt < 4; nt++) {
            int rbase = m0 + wm + mt * 16 + g;
            int col = n0 + wn + nt * 8 + 2 * tig;
#pragma unroll
            for (int hh = 0; hh < 2; hh++) {
                int r = rbase + hh * 8;
                float v0 = acc[mt][nt][hh * 2 + 0] + bias[col];
                float v1 = acc[mt][nt][hh * 2 + 1] + bias[col + 1];
                if (EPI == 1) {
                    v0 = 0.5f * v0 * (1.0f + erff(v0 * 0.70710678118654752f));
                    v1 = 0.5f * v1 * (1.0f + erff(v1 * 0.70710678118654752f));
                }
                size_t gi = (size_t)r * N + col;
                if (EPI == 2) {
                    float* C = (float*)Cv;
                    *(float2*)(C + gi) = make_float2(v0 + res[gi], v1 + res[gi + 1]);
                } else {
                    bf16* C = (bf16*)Cv;
                    *(uint32_t*)(C + gi) = pack_bf2(v0, v1);
                }
            }
        }
    }
}

// Merged Q/K/V projection GEMM: grid (3, 480); by<320 -> Q, <400 -> K, else V.
__global__ void __launch_bounds__(256, 2)
gemm_proj(const bf16* __restrict__ Aq, const bf16* __restrict__ Wq, const float* __restrict__ bq, bf16* __restrict__ Cq,
          const bf16* __restrict__ Ak, const bf16* __restrict__ Wk, const float* __restrict__ bk, bf16* __restrict__ Ck,
          const bf16* __restrict__ Av, const bf16* __restrict__ Wv, const float* __restrict__ bv, bf16* __restrict__ Cv2) {
    extern __shared__ bf16 smem_bf[];
    uint32_t smem_u32 = (uint32_t)__cvta_generic_to_shared(smem_bf);
    int by = blockIdx.y;
    const bf16 *A, *W; const float* bias; bf16* C;
    if (by < 320)      { A = Aq; W = Wq; bias = bq; C = Cq; }
    else if (by < 400) { A = Ak; W = Wk; bias = bk; C = Ck; by -= 320; }
    else               { A = Av; W = Wv; bias = bv; C = Cv2; by -= 400; }

    int n0 = blockIdx.x * 128, m0 = by * 128;
    int t = threadIdx.x;
    int row = t >> 1, half = t & 1;
    int lane = t & 31, g = lane >> 2, tig = lane & 3;
    int w = t >> 5;
    int wm = (w >> 2) * 64, wn = (w & 3) * 32;

    GemmCtx cx; gemm_ctx_init(cx, smem_u32);
    const bf16* Asrc = A + (size_t)(m0 + row) * DIM + half * 16;
    const bf16* Bsrc = W + (size_t)(n0 + row) * DIM + half * 16;
    float acc[4][4][4] = {};
    gemm_mainloop(cx, smem_u32, Asrc, Bsrc, DIM >> 5, acc);

#pragma unroll
    for (int mt = 0; mt < 4; mt++) {
#pragma unroll
        for (int nt = 0; nt < 4; nt++) {
            int rbase = m0 + wm + mt * 16 + g;
            int col = n0 + wn + nt * 8 + 2 * tig;
#pragma unroll
            for (int hh = 0; hh < 2; hh++) {
                int r = rbase + hh * 8;
                float v0 = acc[mt][nt][hh * 2 + 0] + bias[col];
                float v1 = acc[mt][nt][hh * 2 + 1] + bias[col + 1];
                *(uint32_t*)(C + (size_t)r * DIM + col) = pack_bf2(v0, v1);
            }
        }
    }
}

// ---------------------------------------------------------------------------
// Fused flash attention, base-2 online softmax, cp.async K/V + ldmatrix.
// grid: (20, B*H): bx 0..15 search (nkv=320), 16..19 target (nkv=64).
// ---------------------------------------------------------------------------
__global__ void __launch_bounds__(128)
attn_fused(const bf16* __restrict__ Q, const bf16* __restrict__ Kg,
           const bf16* __restrict__ Vg, const float* __restrict__ x,
           float* __restrict__ x2) {
    __shared__ __align__(16) bf16 Qs[64][56];
    __shared__ __align__(16) bf16 Ks[2][64][56];
    __shared__ __align__(16) bf16 Vs[2][64][56];
    __shared__ __align__(16) bf16 Ps[4][16][72];

    int bh = blockIdx.y, b = bh >> 3, h = bh & 7;
    int bx = blockIdx.x;
    int q_base, kv_base, niter;
    if (bx < 16) { q_base = bx * 64;               kv_base = 0;   niter = 5; }
    else         { q_base = 1024 + (bx - 16) * 64; kv_base = 256; niter = 1; }

    int t = threadIdx.x;
    int w = t >> 5, lane = t & 31, g = lane >> 2, tig = lane & 3;
    int wrow = w * 16;

    uint32_t qs_u32 = (uint32_t)__cvta_generic_to_shared(&Qs[0][0]);
    uint32_t ks_u32 = (uint32_t)__cvta_generic_to_shared(&Ks[0][0][0]);
    uint32_t vs_u32 = (uint32_t)__cvta_generic_to_shared(&Vs[0][0][0]);

    for (int idx = t; idx < 384; idx += 128) {
        int r = idx / 6, c8 = (idx % 6) * 8;
        uint4 raw = *(const uint4*)(Q + (size_t)(b * NTOK + q_base + r) * DIM + h * HDIM + c8);
        *(uint2*)&Qs[r][c8]     = make_uint2(raw.x, raw.y);
        *(uint2*)&Qs[r][c8 + 4] = make_uint2(raw.z, raw.w);
    }

    {
        const bf16* kbase = Kg + (size_t)(b * NKV + kv_base) * DIM + h * HDIM;
        const bf16* vbase = Vg + (size_t)(b * NKV + kv_base) * DIM + h * HDIM;
#pragma unroll
        for (int j0 = 0; j0 < 768; j0 += 128) {
            int j = j0 + t;
            int hv = j >= 384;
            int jj = hv ? j - 384 : j;
            int r = jj / 6, c8 = (jj % 6) * 8;
            const bf16* src = (hv ? vbase : kbase) + (size_t)r * DIM + c8;
            uint32_t dst = (hv ? vs_u32 : ks_u32) + (uint32_t)((r * 56 + c8) * 2);
            CP_A16(dst, src);
        }
        CP_COMMIT();
    }
    __syncthreads();

    uint32_t qf[3][4];
    {
        uint32_t qaddr = qs_u32 + (uint32_t)(((wrow + (lane & 15)) * 56 + (lane >> 4) * 8) * 2);
#pragma unroll
        for (int kt = 0; kt < 3; kt++)
            ldsm_x4(qaddr + kt * 32, qf[kt]);
    }

    uint32_t kaddr0 = ks_u32 + (uint32_t)((((lane & 7) + ((lane >> 4) & 1) * 8) * 56
                                           + ((lane >> 3) & 1) * 8) * 2);
    uint32_t vaddr0 = vs_u32 + (uint32_t)(((lane & 15) * 56 + (lane >> 4) * 8) * 2);

    float m0r = -1e30f, m1r = -1e30f, l0 = 0.0f, l1 = 0.0f;
    float oacc[6][4] = {};
    uint32_t* Pw = (uint32_t*)&Ps[w][0][0];

    for (int i = 0; i < niter; i++) {
        CP_WAIT0();
        __syncthreads();

        if (i + 1 < niter) {
            int k0n = (i + 1) * 64;
            uint32_t bufo = (uint32_t)(((i + 1) & 1) * 7168);
            const bf16* kbase = Kg + (size_t)(b * NKV + kv_base + k0n) * DIM + h * HDIM;
            const bf16* vbase = Vg + (size_t)(b * NKV + kv_base + k0n) * DIM + h * HDIM;
#pragma unroll
            for (int j0 = 0; j0 < 768; j0 += 128) {
                int j = j0 + t;
                int hv = j >= 384;
                int jj = hv ? j - 384 : j;
                int r = jj / 6, c8 = (jj % 6) * 8;
                const bf16* src = (hv ? vbase : kbase) + (size_t)r * DIM + c8;
                uint32_t dst = (hv ? vs_u32 : ks_u32) + bufo + (uint32_t)((r * 56 + c8) * 2);
                CP_A16(dst, src);
            }
        }
        CP_COMMIT();

        uint32_t bufc = (uint32_t)((i & 1) * 7168);

        // S' = Q @ K^T * (scale*log2e)
        float sf[8][4] = {};
#pragma unroll
        for (int kt = 0; kt < 3; kt++) {
#pragma unroll
            for (int p = 0; p < 4; p++) {
                uint32_t kb[4];
                ldsm_x4(kaddr0 + bufc + (uint32_t)(p * 16 * 112 + kt * 32), kb);
                uint32_t b0[2] = { kb[0], kb[1] };
                uint32_t b1[2] = { kb[2], kb[3] };
                mma_bf16(sf[2 * p],     qf[kt], b0);
                mma_bf16(sf[2 * p + 1], qf[kt], b1);
            }
        }
#pragma unroll
        for (int nt = 0; nt < 8; nt++) {
            sf[nt][0] *= ATT_SC2; sf[nt][1] *= ATT_SC2;
            sf[nt][2] *= ATT_SC2; sf[nt][3] *= ATT_SC2;
        }

        float tm0 = -1e30f, tm1 = -1e30f;
#pragma unroll
        for (int nt = 0; nt < 8; nt++) {
            tm0 = fmaxf(tm0, fmaxf(sf[nt][0], sf[nt][1]));
            tm1 = fmaxf(tm1, fmaxf(sf[nt][2], sf[nt][3]));
        }
        tm0 = fmaxf(tm0, __shfl_xor_sync(0xffffffffu, tm0, 1));
        tm0 = fmaxf(tm0, __shfl_xor_sync(0xffffffffu, tm0, 2));
        tm1 = fmaxf(tm1, __shfl_xor_sync(0xffffffffu, tm1, 1));
        tm1 = fmaxf(tm1, __shfl_xor_sync(0xffffffffu, tm1, 2));
        float nm0 = fmaxf(m0r, tm0), nm1 = fmaxf(m1r, tm1);
        float f0 = ex2f(m0r - nm0), f1 = ex2f(m1r - nm1);
        m0r = nm0; m1r = nm1;
        l0 *= f0; l1 *= f1;
#pragma unroll
        for (int nt = 0; nt < 6; nt++) {
            oacc[nt][0] *= f0; oacc[nt][1] *= f0;
            oacc[nt][2] *= f1; oacc[nt][3] *= f1;
        }
#pragma unroll
        for (int nt = 0; nt < 8; nt++) {
            float p0 = ex2f(sf[nt][0] - m0r);
            float p1 = ex2f(sf[nt][1] - m0r);
            float p2 = ex2f(sf[nt][2] - m1r);
            float p3 = ex2f(sf[nt][3] - m1r);
            l0 += p0 + p1; l1 += p2 + p3;
            Pw[(g    ) * 36 + nt * 4 + tig] = pack_bf2(p0, p1);
            Pw[(g + 8) * 36 + nt * 4 + tig] = pack_bf2(p2, p3);
        }
        __syncwarp();

#pragma unroll
        for (int ks = 0; ks < 4; ks++) {
            uint32_t pa[4];
            pa[0] = Pw[(g    ) * 36 + ks * 8 + tig];
            pa[1] = Pw[(g + 8) * 36 + ks * 8 + tig];
            pa[2] = Pw[(g    ) * 36 + ks * 8 + tig + 4];
            pa[3] = Pw[(g + 8) * 36 + ks * 8 + tig + 4];
#pragma unroll
            for (int jv = 0; jv < 3; jv++) {
                uint32_t vv[4];
                ldsm_x4_t(vaddr0 + bufc + (uint32_t)(ks * 16 * 112 + jv * 32), vv);
                uint32_t b0[2] = { vv[0], vv[1] };
                uint32_t b1[2] = { vv[2], vv[3] };
                mma_bf16(oacc[2 * jv],     pa, b0);
                mma_bf16(oacc[2 * jv + 1], pa, b1);
            }
        }
        __syncwarp();
    }

    l0 += __shfl_xor_sync(0xffffffffu, l0, 1);
    l0 += __shfl_xor_sync(0xffffffffu, l0, 2);
    l1 += __shfl_xor_sync(0xffffffffu, l1, 1);
    l1 += __shfl_xor_sync(0xffffffffu, l1, 2);
    float inv0 = 1.0f / l0, inv1 = 1.0f / l1;
    int r0 = b * NTOK + q_base + wrow + g;
#pragma unroll
    for (int nt = 0; nt < 6; nt++) {
        int col = h * HDIM + nt * 8 + 2 * tig;
        size_t gi0 = (size_t)r0 * DIM + col;
        size_t gi1 = (size_t)(r0 + 8) * DIM + col;
        float2 xa = *(const float2*)(x + gi0);
        float2 xb = *(const float2*)(x + gi1);
        *(float2*)(x2 + gi0) = make_float2(xa.x + oacc[nt][0] * inv0, xa.y + oacc[nt][1] * inv0);
        *(float2*)(x2 + gi1) = make_float2(xb.x + oacc[nt][2] * inv1, xb.y + oacc[nt][3] * inv1);
    }
}

// ---------------------------------------------------------------------------
// Launch
// ---------------------------------------------------------------------------
extern "C" void kernel_launch(void* const* d_in, const int* in_sizes, int n_in,
                              void* d_out, int out_size) {
    (void)in_sizes; (void)n_in; (void)out_size;
    const float* x     = (const float*)d_in[0];
    const float* ln1_g = (const float*)d_in[1];
    const float* ln1_b = (const float*)d_in[2];
    const float* dwq_w = (const float*)d_in[3];
    const float* dwq_b = (const float*)d_in[4];
    const float* bnq_g = (const float*)d_in[5];
    const float* bnq_b = (const float*)d_in[6];
    const float* dwk_w = (const float*)d_in[7];
    const float* dwk_b = (const float*)d_in[8];
    const float* bnk_g = (const float*)d_in[9];
    const float* bnk_b = (const float*)d_in[10];
    const float* dwv_w = (const float*)d_in[11];
    const float* dwv_b = (const float*)d_in[12];
    const float* bnv_g = (const float*)d_in[13];
    const float* bnv_b = (const float*)d_in[14];
    const float* pq_w  = (const float*)d_in[15];
    const float* pq_b  = (const float*)d_in[16];
    const float* pk_w  = (const float*)d_in[17];
    const float* pk_b  = (const float*)d_in[18];
    const float* pv_w  = (const float*)d_in[19];
    const float* pv_b  = (const float*)d_in[20];
    const float* ln2_g = (const float*)d_in[21];
    const float* ln2_b = (const float*)d_in[22];
    const float* ff1_w = (const float*)d_in[23];
    const float* ff1_b = (const float*)d_in[24];
    const float* ff2_w = (const float*)d_in[25];
    const float* ff2_b = (const float*)d_in[26];
    float* out = (float*)d_out;

    bf16 *xn, *qc, *kc, *vc, *Q, *K, *V, *h1, *wq, *wk, *wv, *w1, *w2;
    float *x2;
    cudaGetSymbolAddress((void**)&xn, g_xn);
    cudaGetSymbolAddress((void**)&qc, g_qc);
    cudaGetSymbolAddress((void**)&kc, g_kc);
    cudaGetSymbolAddress((void**)&vc, g_vc);
    cudaGetSymbolAddress((void**)&Q,  g_Q);
    cudaGetSymbolAddress((void**)&K,  g_K);
    cudaGetSymbolAddress((void**)&V,  g_V);
    cudaGetSymbolAddress((void**)&x2, g_x2);
    cudaGetSymbolAddress((void**)&h1, g_h1);
    cudaGetSymbolAddress((void**)&wq, g_wq);
    cudaGetSymbolAddress((void**)&wk, g_wk);
    cudaGetSymbolAddress((void**)&wv, g_wv);
    cudaGetSymbolAddress((void**)&w1, g_w1);
    cudaGetSymbolAddress((void**)&w2, g_w2);

    cudaFuncSetAttribute(gemm_bf<1>, cudaFuncAttributeMaxDynamicSharedMemorySize, 61440);
    cudaFuncSetAttribute(gemm_bf<2>, cudaFuncAttributeMaxDynamicSharedMemorySize, 61440);
    cudaFuncSetAttribute(gemm_proj,  cudaFuncAttributeMaxDynamicSharedMemorySize, 61440);

    // 1. Weight conversion + LN1 (single fused launch)
    cvt_ln1<<<1584 + BATCH * NTOK / 8, 256>>>(pq_w, wq, pk_w, wk, pv_w, wv,
                                              ff1_w, w1, ff2_w, w2,
                                              x, ln1_g, ln1_b, xn);

    // 2. All depthwise convs in one launch (q 40960 + k 10240 + v 10240 blocks)
    dwconv_all<<<BATCH * 1280 + 2 * BATCH * 320, 192>>>(
        xn,
        dwq_w, dwq_b, bnq_g, bnq_b,
        dwk_w, dwk_b, bnk_g, bnk_b,
        dwv_w, dwv_b, bnv_g, bnv_b,
        qc, kc, vc);

    // 3. Q/K/V projections — single merged launch
    gemm_proj<<<dim3(3, 480), 256, 61440>>>(qc, wq, pq_b, Q,
                                            kc, wk, pk_b, K,
                                            vc, wv, pv_b, V);

    // 4. Fused flash attention (+ residual)
    attn_fused<<<dim3(20, BATCH * HEADS), 128>>>(Q, K, V, x, x2);

    // 5. LN2 + FFN
    ln_kernel<<<BATCH * NTOK / 8, 256>>>(x2, ln2_g, ln2_b, xn);
    gemm_bf<1><<<dim3(12, 320), 256, 61440>>>(xn, w1, ff1_b, nullptr, h1, BATCH * NTOK, FFDIM, DIM);
    gemm_bf<2><<<dim3(3, 320),  256, 61440>>>(h1, w2, ff2_b, x2, out, BATCH * NTOK, DIM, FFDIM);
}